// round 10
// baseline (speedup 1.0000x reference)
#include <cuda_runtime.h>
#include <math.h>
#include <stdint.h>

// Problem: tensor [8192, 256] fp32.
// out = (adj @ X) where adj = rownorm(cosine_sim(X)).
// Factored: M = X_hat^T X (256x256, SYMMETRIC), s = sum_j x_hat_j (256),
//           out[i] = (x_i @ M) / (x_i . s)   (inv-norm cancels).
// Denominator via compensated fp32 (Dot2).
// k_out: warp-level mma.sync TF32 (sm_80 PTX -> HMMA; tcgen05 unavailable:
// harness compiles compute_103 without the 'a' feature set), 3-term split
// (hh + hl + lh) with fp32 accumulation -> ~2^-22 product error.

#define NROWS 8192
#define DDIM  256
#define GCHUNKS 64
#define SCHUNKS 256
#define NTILES  10

__device__ float  g_invn[NROWS];
__device__ float2 g_spart[SCHUNKS][DDIM];
__device__ float2 g_s2[DDIM];
__device__ float  g_rinv[NROWS];
__device__ float  g_Mpart[GCHUNKS][NTILES][64 * 64];
__device__ float  g_Mh[DDIM * DDIM];   // tf32-high part of M
__device__ float  g_Ml[DDIM * DDIM];   // tf32-low  part of M

__device__ const int c_TI[NTILES] = {0,0,0,0,1,1,1,2,2,3};
__device__ const int c_TJ[NTILES] = {0,1,2,3,1,2,3,2,3,3};

// ---- error-free fp32 transforms ------------------------------------------
__device__ __forceinline__ void twoSum(float a, float b, float& s, float& e) {
    s = a + b;
    float bb = s - a;
    e = (a - (s - bb)) + (b - bb);
}
__device__ __forceinline__ void twoProd(float a, float b, float& p, float& e) {
    p = a * b;
    e = fmaf(a, b, -p);
}

// ---- tf32 split ------------------------------------------------------------
__device__ __forceinline__ void tf32split(float x, float& h, float& l) {
    uint32_t hu, lu;
    asm("cvt.rna.tf32.f32 %0, %1;" : "=r"(hu) : "f"(x));
    h = __uint_as_float(hu);
    asm("cvt.rna.tf32.f32 %0, %1;" : "=r"(lu) : "f"(x - h));
    l = __uint_as_float(lu);
}

// ---- warp mma m16n8k8 tf32 --------------------------------------------------
__device__ __forceinline__ void mma_tf32(float* c, uint32_t a0, uint32_t a1,
                                         uint32_t a2, uint32_t a3,
                                         uint32_t b0, uint32_t b1) {
    asm volatile(
        "mma.sync.aligned.m16n8k8.row.col.f32.tf32.tf32.f32 "
        "{%0,%1,%2,%3}, {%4,%5,%6,%7}, {%8,%9}, {%0,%1,%2,%3};"
        : "+f"(c[0]), "+f"(c[1]), "+f"(c[2]), "+f"(c[3])
        : "r"(a0), "r"(a1), "r"(a2), "r"(a3), "r"(b0), "r"(b1));
}

// ---------------------------------------------------------------------------
// Kernel 1: per-row inverse norms + compensated fp32 partial column sums.
// ---------------------------------------------------------------------------
__global__ void __launch_bounds__(256) k_norm_s(const float* __restrict__ X) {
    __shared__ float invn_sh[32];
    const int row0 = blockIdx.x * 32;
    const int wid  = threadIdx.x >> 5;
    const int lane = threadIdx.x & 31;

    for (int r = wid; r < 32; r += 8) {
        const float4* p = reinterpret_cast<const float4*>(X + (size_t)(row0 + r) * DDIM);
        float ss = 0.f;
        #pragma unroll
        for (int q = 0; q < 2; q++) {
            float4 v = p[lane + q * 32];
            ss += v.x * v.x + v.y * v.y + v.z * v.z + v.w * v.w;
        }
        #pragma unroll
        for (int o = 16; o > 0; o >>= 1) ss += __shfl_xor_sync(0xffffffffu, ss, o);
        if (lane == 0) {
            float inv = 1.0f / fmaxf(sqrtf(ss), 1e-8f);
            invn_sh[r]       = inv;
            g_invn[row0 + r] = inv;
        }
    }
    __syncthreads();

    const int t = threadIdx.x;
    float s = 0.f, c = 0.f;
    #pragma unroll
    for (int r = 0; r < 32; r++) {
        float p, e, t1;
        twoProd(invn_sh[r], X[(size_t)(row0 + r) * DDIM + t], p, e);
        twoSum(s, p, s, t1);
        c += t1 + e;
    }
    g_spart[blockIdx.x][t] = make_float2(s, c);
}

// ---------------------------------------------------------------------------
// Kernel 2: partial Gram, upper-triangle tiles (SIMT, proven R5 shape).
// ---------------------------------------------------------------------------
__global__ void __launch_bounds__(256) k_gram(const float* __restrict__ X) {
    __shared__ float SA[8][64];
    __shared__ float SB[8][64];

    const int c  = blockIdx.x;
    const int t  = blockIdx.y;
    const int ti = c_TI[t];
    const int tj = c_TJ[t];
    const int tx = threadIdx.x & 15;
    const int ty = (threadIdx.x >> 4) & 15;
    const int side = threadIdx.x >> 7;
    const int li   = (threadIdx.x >> 4) & 7;
    const int lf   = threadIdx.x & 15;
    const int rowbase = c * 128;
    const int colbase = (side == 0 ? ti : tj) * 64;

    float T[4][4];
    #pragma unroll
    for (int i = 0; i < 4; i++)
        #pragma unroll
        for (int j = 0; j < 4; j++) T[i][j] = 0.f;

    for (int kk = 0; kk < 128; kk += 8) {
        const int gr = rowbase + kk + li;
        float4 v = *reinterpret_cast<const float4*>(X + (size_t)gr * DDIM + colbase + lf * 4);
        float scale = (side == 0) ? g_invn[gr] : 1.0f;
        __syncthreads();
        if (side == 0)
            *reinterpret_cast<float4*>(&SA[li][lf * 4]) =
                make_float4(v.x * scale, v.y * scale, v.z * scale, v.w * scale);
        else
            *reinterpret_cast<float4*>(&SB[li][lf * 4]) = v;
        __syncthreads();
        #pragma unroll
        for (int r = 0; r < 8; r++) {
            float4 a = *reinterpret_cast<const float4*>(&SA[r][ty * 4]);
            float4 b = *reinterpret_cast<const float4*>(&SB[r][tx * 4]);
            const float aa[4] = {a.x, a.y, a.z, a.w};
            const float bb[4] = {b.x, b.y, b.z, b.w};
            #pragma unroll
            for (int i = 0; i < 4; i++)
                #pragma unroll
                for (int j = 0; j < 4; j++) T[i][j] += aa[i] * bb[j];
        }
    }

    float* out = &g_Mpart[c][t][0];
    #pragma unroll
    for (int i = 0; i < 4; i++)
        *reinterpret_cast<float4*>(&out[(ty * 4 + i) * 64 + tx * 4]) =
            make_float4(T[i][0], T[i][1], T[i][2], T[i][3]);
}

// ---------------------------------------------------------------------------
// Kernel 3: compensated reduce of Mpart; writes tf32-split M (high/low) with
// symmetric mirror. Also folds the s-partial pairs.
// ---------------------------------------------------------------------------
__global__ void __launch_bounds__(256) k_reduce() {
    const int idx = blockIdx.x * 256 + threadIdx.x;
    const int t = idx >> 12;
    const int e = idx & 4095;
    float s = 0.f, comp = 0.f;
    #pragma unroll
    for (int c = 0; c < GCHUNKS; c++) {
        float t1;
        twoSum(s, g_Mpart[c][t][e], s, t1);
        comp += t1;
    }
    const float v = s + comp;
    float vh, vl;
    tf32split(v, vh, vl);
    const int k = c_TI[t] * 64 + (e >> 6);
    const int l = c_TJ[t] * 64 + (e & 63);
    if (k < l) {
        g_Mh[k * DDIM + l] = vh;  g_Ml[k * DDIM + l] = vl;
        g_Mh[l * DDIM + k] = vh;  g_Ml[l * DDIM + k] = vl;
    } else if (k == l) {
        g_Mh[k * DDIM + l] = vh;  g_Ml[k * DDIM + l] = vl;
    }

    if (blockIdx.x == 0) {
        float sa = 0.f, ca = 0.f;
        #pragma unroll 8
        for (int b = 0; b < SCHUNKS; b++) {
            float2 p = g_spart[b][threadIdx.x];
            float t1;
            twoSum(sa, p.x, sa, t1);
            ca += t1 + p.y;
        }
        g_s2[threadIdx.x] = make_float2(sa, ca);
    }
}

// ---------------------------------------------------------------------------
// Kernel 4: rinv[i] = 1 / (x_i . s) via Dot2, one row per warp (R5-proven).
// ---------------------------------------------------------------------------
__global__ void __launch_bounds__(256) k_rinv(const float* __restrict__ X) {
    __shared__ float2 s_sh[DDIM];
    s_sh[threadIdx.x] = g_s2[threadIdx.x];
    __syncthreads();
    const int wid  = threadIdx.x >> 5;
    const int lane = threadIdx.x & 31;
    const int row  = blockIdx.x * 8 + wid;

    const float4* xp4 = reinterpret_cast<const float4*>(X + (size_t)row * DDIM);
    float s = 0.f, c = 0.f;
    #pragma unroll
    for (int q = 0; q < 2; q++) {
        const int f = lane + q * 32;
        const float4 xv = xp4[f];
        const float xs[4] = {xv.x, xv.y, xv.z, xv.w};
        #pragma unroll
        for (int m = 0; m < 4; m++) {
            const float2 sv = s_sh[f * 4 + m];
            float p, e, t1;
            twoProd(xs[m], sv.x, p, e);
            e = fmaf(xs[m], sv.y, e);
            twoSum(s, p, s, t1);
            c += t1 + e;
        }
    }
    #pragma unroll
    for (int o = 16; o > 0; o >>= 1) {
        float s2 = __shfl_xor_sync(0xffffffffu, s, o);
        float c2 = __shfl_xor_sync(0xffffffffu, c, o);
        float t1;
        twoSum(s, s2, s, t1);
        c += c2 + t1;
    }
    if (lane == 0) {
        double den = (double)s + (double)c;
        g_rinv[row] = (float)(1.0 / den);
    }
}

// ---------------------------------------------------------------------------
// Kernel 5: OUT = (X @ M) * rinv, TF32 mma.sync, 3-term split.
// Block: 128 rows x 128 cols, 8 warps (4x2), warp tile 32x64.
// Grid (64, 2) = 128 CTAs = one wave. K: 8 panels of 32.
// Smem strides: X 36 floats/row, M 136 floats/row -> conflict-free frags.
// ---------------------------------------------------------------------------
#define XLD 36
#define MLD 136
#define KOUT_SMEM ((2 * 128 * XLD + 2 * 32 * MLD) * 4)   // 71680 B

__global__ void __launch_bounds__(256) k_out_tc(const float* __restrict__ X,
                                                float* __restrict__ OUT) {
    extern __shared__ float sm[];
    float* XHs = sm;                    // [128][36]
    float* XLs = XHs + 128 * XLD;
    float* MHs = XLs + 128 * XLD;       // [32][136]
    float* MLs = MHs + 32 * MLD;

    const int tid  = threadIdx.x;
    const int wid  = tid >> 5;
    const int lane = tid & 31;
    const int gid  = lane >> 2;         // 0..7
    const int tig  = lane & 3;          // 0..3
    const int wr   = wid >> 1;          // 0..3  warp row
    const int wc   = wid & 1;           // 0..1  warp col
    const int row0 = blockIdx.x * 128;
    const int c0   = blockIdx.y * 128;

    float C[2][8][4];
    #pragma unroll
    for (int mf = 0; mf < 2; mf++)
        #pragma unroll
        for (int nf = 0; nf < 8; nf++)
            #pragma unroll
            for (int q = 0; q < 4; q++) C[mf][nf][q] = 0.f;

    for (int p = 0; p < 8; p++) {
        const int k0 = p * 32;
        __syncthreads();   // previous panel's smem reads done

        // stage X panel [128 rows x 32 k], split inline
        #pragma unroll
        for (int q = 0; q < 4; q++) {
            const int u = tid + q * 256;
            const int r = u >> 3, cg = u & 7;
            float4 v = *reinterpret_cast<const float4*>(
                X + (size_t)(row0 + r) * DDIM + k0 + cg * 4);
            float hx, lx, hy, ly, hz, lz, hw, lw;
            tf32split(v.x, hx, lx); tf32split(v.y, hy, ly);
            tf32split(v.z, hz, lz); tf32split(v.w, hw, lw);
            const int o = r * XLD + cg * 4;
            *reinterpret_cast<float4*>(&XHs[o]) = make_float4(hx, hy, hz, hw);
            *reinterpret_cast<float4*>(&XLs[o]) = make_float4(lx, ly, lz, lw);
        }
        // stage M panel [32 k x 128 n] from pre-split g_Mh/g_Ml
        #pragma unroll
        for (int q = 0; q < 4; q++) {
            const int u = tid + q * 256;
            const int kk = u >> 5, c4 = u & 31;
            const int go = (k0 + kk) * DDIM + c0 + c4 * 4;
            const int o  = kk * MLD + c4 * 4;
            *reinterpret_cast<float4*>(&MHs[o]) =
                *reinterpret_cast<const float4*>(&g_Mh[go]);
            *reinterpret_cast<float4*>(&MLs[o]) =
                *reinterpret_cast<const float4*>(&g_Ml[go]);
        }
        __syncthreads();

        #pragma unroll
        for (int ks = 0; ks < 4; ks++) {
            const int kb = ks * 8;
            // A fragments (h and l) for both m-frags
            uint32_t ah[2][4], al[2][4];
            #pragma unroll
            for (int mf = 0; mf < 2; mf++) {
                const int ra = wr * 32 + mf * 16 + gid;
                const int o0 = ra * XLD + kb + tig;
                const int o1 = (ra + 8) * XLD + kb + tig;
                ah[mf][0] = __float_as_uint(XHs[o0]);
                ah[mf][1] = __float_as_uint(XHs[o1]);
                ah[mf][2] = __float_as_uint(XHs[o0 + 4]);
                ah[mf][3] = __float_as_uint(XHs[o1 + 4]);
                al[mf][0] = __float_as_uint(XLs[o0]);
                al[mf][1] = __float_as_uint(XLs[o1]);
                al[mf][2] = __float_as_uint(XLs[o0 + 4]);
                al[mf][3] = __float_as_uint(XLs[o1 + 4]);
            }
            #pragma unroll
            for (int nf = 0; nf < 8; nf++) {
                const int cn = wc * 64 + nf * 8 + gid;
                const uint32_t bh0 = __float_as_uint(MHs[(kb + tig) * MLD + cn]);
                const uint32_t bh1 = __float_as_uint(MHs[(kb + tig + 4) * MLD + cn]);
                const uint32_t bl0 = __float_as_uint(MLs[(kb + tig) * MLD + cn]);
                const uint32_t bl1 = __float_as_uint(MLs[(kb + tig + 4) * MLD + cn]);
                #pragma unroll
                for (int mf = 0; mf < 2; mf++) {
                    mma_tf32(C[mf][nf], ah[mf][0], ah[mf][1], ah[mf][2], ah[mf][3], bh0, bh1);
                    mma_tf32(C[mf][nf], al[mf][0], al[mf][1], al[mf][2], al[mf][3], bh0, bh1);
                    mma_tf32(C[mf][nf], ah[mf][0], ah[mf][1], ah[mf][2], ah[mf][3], bl0, bl1);
                }
            }
        }
    }

    // epilogue: scale by rinv and store (float2 per c-pair)
    #pragma unroll
    for (int mf = 0; mf < 2; mf++) {
        const int r0 = row0 + wr * 32 + mf * 16 + gid;
        const int r1 = r0 + 8;
        const float rv0 = g_rinv[r0];
        const float rv1 = g_rinv[r1];
        #pragma unroll
        for (int nf = 0; nf < 8; nf++) {
            const int cn = c0 + wc * 64 + nf * 8 + tig * 2;
            *reinterpret_cast<float2*>(&OUT[(size_t)r0 * DDIM + cn]) =
                make_float2(C[mf][nf][0] * rv0, C[mf][nf][1] * rv0);
            *reinterpret_cast<float2*>(&OUT[(size_t)r1 * DDIM + cn]) =
                make_float2(C[mf][nf][2] * rv1, C[mf][nf][3] * rv1);
        }
    }
}

extern "C" void kernel_launch(void* const* d_in, const int* in_sizes, int n_in,
                              void* d_out, int out_size) {
    (void)in_sizes; (void)n_in; (void)out_size;
    const float* X = (const float*)d_in[0];
    float* OUT     = (float*)d_out;

    cudaFuncSetAttribute(k_out_tc, cudaFuncAttributeMaxDynamicSharedMemorySize,
                         KOUT_SMEM);

    k_norm_s<<<SCHUNKS, 256>>>(X);
    k_gram<<<dim3(GCHUNKS, NTILES), 256>>>(X);
    k_reduce<<<160, 256>>>();
    k_rinv<<<1024, 256>>>(X);
    k_out_tc<<<dim3(64, 2), 256, KOUT_SMEM>>>(X, OUT);
}

// round 11
// speedup vs baseline: 1.1867x; 1.1867x over previous
#include <cuda_runtime.h>
#include <math.h>

// Problem: tensor [8192, 256] fp32.
// out = (adj @ X) where adj = rownorm(cosine_sim(X)).
// Factored: M = X_hat^T X (256x256, SYMMETRIC), s = sum_j x_hat_j (256),
//           out[i] = (x_i @ M) / (x_i . s)   (inv-norm cancels).
// Denominator via compensated fp32 Dot2 (fp64-grade accuracy; B300 FP64 is
// de-rated). Tensor paths measured/closed: tcgen05 won't compile on the
// harness's sm_103 (no 'a'), mma.sync TF32 fallback is not faster than the
// scalar-FFMA roofline. 4 kernels; rinv fused into k_out's prologue.

#define NROWS 8192
#define DDIM  256
#define GCHUNKS 64          // gram K-chunks: 128 rows each
#define SCHUNKS 256         // norm/s blocks: 32 rows each
#define NTILES  10          // upper-triangle 64x64 tiles of the 4x4 tile grid

__device__ float  g_invn[NROWS];
__device__ float2 g_spart[SCHUNKS][DDIM];   // compensated fp32 pairs (hi, lo)
__device__ float2 g_s2[DDIM];
__device__ float  g_Mpart[GCHUNKS][NTILES][64 * 64];
__device__ float  g_M[DDIM * DDIM];

__device__ const int c_TI[NTILES] = {0,0,0,0,1,1,1,2,2,3};
__device__ const int c_TJ[NTILES] = {0,1,2,3,1,2,3,2,3,3};

// ---- error-free fp32 transforms ------------------------------------------
__device__ __forceinline__ void twoSum(float a, float b, float& s, float& e) {
    s = a + b;
    float bb = s - a;
    e = (a - (s - bb)) + (b - bb);
}
__device__ __forceinline__ void twoProd(float a, float b, float& p, float& e) {
    p = a * b;
    e = fmaf(a, b, -p);
}

// ---------------------------------------------------------------------------
// Kernel 1: per-row inverse norms + compensated fp32 partial column sums of
// X_hat. 256 blocks x 256 threads; block b handles rows [b*32, +32).
// ---------------------------------------------------------------------------
__global__ void __launch_bounds__(256) k_norm_s(const float* __restrict__ X) {
    __shared__ float invn_sh[32];
    const int row0 = blockIdx.x * 32;
    const int wid  = threadIdx.x >> 5;
    const int lane = threadIdx.x & 31;

    for (int r = wid; r < 32; r += 8) {
        const float4* p = reinterpret_cast<const float4*>(X + (size_t)(row0 + r) * DDIM);
        float ss = 0.f;
        #pragma unroll
        for (int q = 0; q < 2; q++) {
            float4 v = p[lane + q * 32];
            ss += v.x * v.x + v.y * v.y + v.z * v.z + v.w * v.w;
        }
        #pragma unroll
        for (int o = 16; o > 0; o >>= 1) ss += __shfl_xor_sync(0xffffffffu, ss, o);
        if (lane == 0) {
            float inv = 1.0f / fmaxf(sqrtf(ss), 1e-8f);
            invn_sh[r]       = inv;
            g_invn[row0 + r] = inv;
        }
    }
    __syncthreads();

    const int t = threadIdx.x;
    float s = 0.f, c = 0.f;
    #pragma unroll
    for (int r = 0; r < 32; r++) {
        float p, e, t1;
        twoProd(invn_sh[r], X[(size_t)(row0 + r) * DDIM + t], p, e);
        twoSum(s, p, s, t1);
        c += t1 + e;
    }
    g_spart[blockIdx.x][t] = make_float2(s, c);
}

// ---------------------------------------------------------------------------
// Kernel 2: partial Gram, upper-triangle tiles only (M is symmetric).
// grid = (64 k-chunks, 10 tiles), 256 threads, 4x4 register tile per thread.
// ---------------------------------------------------------------------------
__global__ void __launch_bounds__(256) k_gram(const float* __restrict__ X) {
    __shared__ float SA[8][64];
    __shared__ float SB[8][64];

    const int c  = blockIdx.x;
    const int t  = blockIdx.y;
    const int ti = c_TI[t];
    const int tj = c_TJ[t];
    const int tx = threadIdx.x & 15;
    const int ty = (threadIdx.x >> 4) & 15;
    const int side = threadIdx.x >> 7;          // warps 0-3 load SA, 4-7 load SB
    const int li   = (threadIdx.x >> 4) & 7;    // stage row 0..7
    const int lf   = threadIdx.x & 15;          // float4 slot 0..15
    const int rowbase = c * 128;
    const int colbase = (side == 0 ? ti : tj) * 64;

    float T[4][4];
    #pragma unroll
    for (int i = 0; i < 4; i++)
        #pragma unroll
        for (int j = 0; j < 4; j++) T[i][j] = 0.f;

    for (int kk = 0; kk < 128; kk += 8) {
        const int gr = rowbase + kk + li;
        float4 v = *reinterpret_cast<const float4*>(X + (size_t)gr * DDIM + colbase + lf * 4);
        float scale = (side == 0) ? g_invn[gr] : 1.0f;
        __syncthreads();   // previous iteration's smem reads done
        if (side == 0)
            *reinterpret_cast<float4*>(&SA[li][lf * 4]) =
                make_float4(v.x * scale, v.y * scale, v.z * scale, v.w * scale);
        else
            *reinterpret_cast<float4*>(&SB[li][lf * 4]) = v;
        __syncthreads();
        #pragma unroll
        for (int r = 0; r < 8; r++) {
            float4 a = *reinterpret_cast<const float4*>(&SA[r][ty * 4]);
            float4 b = *reinterpret_cast<const float4*>(&SB[r][tx * 4]);
            const float aa[4] = {a.x, a.y, a.z, a.w};
            const float bb[4] = {b.x, b.y, b.z, b.w};
            #pragma unroll
            for (int i = 0; i < 4; i++)
                #pragma unroll
                for (int j = 0; j < 4; j++) T[i][j] += aa[i] * bb[j];
        }
    }

    float* out = &g_Mpart[c][t][0];
    #pragma unroll
    for (int i = 0; i < 4; i++)
        *reinterpret_cast<float4*>(&out[(ty * 4 + i) * 64 + tx * 4]) =
            make_float4(T[i][0], T[i][1], T[i][2], T[i][3]);
}

// ---------------------------------------------------------------------------
// Kernel 3: compensated fp32 reduce of Mpart (with symmetric mirror) and the
// s-partial pairs. 160 blocks x 256 threads cover 10*4096 upper-tile elems.
// ---------------------------------------------------------------------------
__global__ void __launch_bounds__(256) k_reduce() {
    const int idx = blockIdx.x * 256 + threadIdx.x;   // 0..40959
    const int t = idx >> 12;
    const int e = idx & 4095;
    float s = 0.f, comp = 0.f;
    #pragma unroll
    for (int c = 0; c < GCHUNKS; c++) {
        float t1;
        twoSum(s, g_Mpart[c][t][e], s, t1);
        comp += t1;
    }
    const float v = s + comp;
    const int k = c_TI[t] * 64 + (e >> 6);
    const int l = c_TJ[t] * 64 + (e & 63);
    if (k < l) {
        g_M[k * DDIM + l] = v;
        g_M[l * DDIM + k] = v;
    } else if (k == l) {
        g_M[k * DDIM + l] = v;
    } // k > l only inside diagonal tiles: mirror writes it

    if (blockIdx.x == 0) {
        float sa = 0.f, ca = 0.f;
        #pragma unroll 8
        for (int b = 0; b < SCHUNKS; b++) {
            float2 p = g_spart[b][threadIdx.x];
            float t1;
            twoSum(sa, p.x, sa, t1);
            ca += t1 + p.y;
        }
        g_s2[threadIdx.x] = make_float2(sa, ca);
    }
}

// ---------------------------------------------------------------------------
// Kernel 4: OUT = (X @ M) / (X . s) rowwise, denominator fused in prologue.
// grid = (128 row tiles, 4 col tiles) = 512 blocks, 256 threads, 4x4/thread.
// Prologue: 8 warps x 8 rows, Dot2 denominator (same rounding as the old
// standalone k_rinv -> identical output bits).
// ---------------------------------------------------------------------------
__global__ void __launch_bounds__(256) k_out(const float* __restrict__ X,
                                             float* __restrict__ OUT) {
    __shared__ float  SA[8][68];
    __shared__ float  SB[8][64];
    __shared__ float2 s_sh[DDIM];
    __shared__ float  rinv_sh[64];

    const int row0 = blockIdx.x * 64;
    const int c0   = blockIdx.y * 64;
    const int tx   = threadIdx.x & 15;
    const int ty   = (threadIdx.x >> 4) & 15;
    const int wid  = threadIdx.x >> 5;
    const int lane = threadIdx.x & 31;

    s_sh[threadIdx.x] = g_s2[threadIdx.x];
    __syncthreads();

    // Fused denominator: warp w handles rows [w*8, w*8+8) of this tile.
    #pragma unroll
    for (int rr = 0; rr < 8; rr++) {
        const int row = row0 + wid * 8 + rr;
        const float4* xp4 = reinterpret_cast<const float4*>(X + (size_t)row * DDIM);
        float s = 0.f, c = 0.f;
        #pragma unroll
        for (int q = 0; q < 2; q++) {
            const int f = lane + q * 32;
            const float4 xv = xp4[f];
            const float xs[4] = {xv.x, xv.y, xv.z, xv.w};
            #pragma unroll
            for (int m = 0; m < 4; m++) {
                const float2 sv = s_sh[f * 4 + m];
                float p, e, t1;
                twoProd(xs[m], sv.x, p, e);
                e = fmaf(xs[m], sv.y, e);
                twoSum(s, p, s, t1);
                c += t1 + e;
            }
        }
        #pragma unroll
        for (int o = 16; o > 0; o >>= 1) {
            float s2 = __shfl_xor_sync(0xffffffffu, s, o);
            float c2 = __shfl_xor_sync(0xffffffffu, c, o);
            float t1;
            twoSum(s, s2, s, t1);
            c += c2 + t1;
        }
        if (lane == 0) {
            double den = (double)s + (double)c;
            rinv_sh[wid * 8 + rr] = (float)(1.0 / den);
        }
    }

    const int ar = threadIdx.x >> 1;          // SA loader: row (tid<128)
    const int ah = threadIdx.x & 1;           // SA loader: k-half
    const int bi = (threadIdx.x >> 4) & 7;    // SB loader: stage row
    const int bf = threadIdx.x & 15;          // SB loader: float4 slot

    float T[4][4];
    #pragma unroll
    for (int i = 0; i < 4; i++)
        #pragma unroll
        for (int j = 0; j < 4; j++) T[i][j] = 0.f;

    for (int k0 = 0; k0 < DDIM; k0 += 8) {
        float4 v;
        if (threadIdx.x < 128)
            v = *reinterpret_cast<const float4*>(X + (size_t)(row0 + ar) * DDIM + k0 + ah * 4);
        else
            v = *reinterpret_cast<const float4*>(&g_M[(k0 + bi) * DDIM + c0 + bf * 4]);
        __syncthreads();
        if (threadIdx.x < 128) {
            SA[ah * 4 + 0][ar] = v.x;
            SA[ah * 4 + 1][ar] = v.y;
            SA[ah * 4 + 2][ar] = v.z;
            SA[ah * 4 + 3][ar] = v.w;
        } else {
            *reinterpret_cast<float4*>(&SB[bi][bf * 4]) = v;
        }
        __syncthreads();
        #pragma unroll
        for (int r = 0; r < 8; r++) {
            float4 a = *reinterpret_cast<const float4*>(&SA[r][ty * 4]);
            float4 b = *reinterpret_cast<const float4*>(&SB[r][tx * 4]);
            const float aa[4] = {a.x, a.y, a.z, a.w};
            const float bb[4] = {b.x, b.y, b.z, b.w};
            #pragma unroll
            for (int i = 0; i < 4; i++)
                #pragma unroll
                for (int j = 0; j < 4; j++) T[i][j] += aa[i] * bb[j];
        }
    }

    #pragma unroll
    for (int i = 0; i < 4; i++) {
        const int m = ty * 4 + i;
        const float rv = rinv_sh[m];
        *reinterpret_cast<float4*>(&OUT[(size_t)(row0 + m) * DDIM + c0 + tx * 4]) =
            make_float4(T[i][0] * rv, T[i][1] * rv, T[i][2] * rv, T[i][3] * rv);
    }
}

extern "C" void kernel_launch(void* const* d_in, const int* in_sizes, int n_in,
                              void* d_out, int out_size) {
    (void)in_sizes; (void)n_in; (void)out_size;
    const float* X = (const float*)d_in[0];
    float* OUT     = (float*)d_out;

    k_norm_s<<<SCHUNKS, 256>>>(X);
    k_gram<<<dim3(GCHUNKS, NTILES), 256>>>(X);
    k_reduce<<<160, 256>>>();
    k_out<<<dim3(128, 4), 256>>>(X, OUT);
}

// round 12
// speedup vs baseline: 1.3469x; 1.1349x over previous
#include <cuda_runtime.h>
#include <math.h>

// Problem: tensor [8192, 256] fp32.
// out = (adj @ X) where adj = rownorm(cosine_sim(X)).
// Factored: M = X_hat^T X (256x256, SYMMETRIC), s = sum_j x_hat_j (256),
//           out[i] = (x_i @ M) / (x_i . s)   (inv-norm cancels).
// Denominator via compensated fp32 Dot2. GEMMs: scalar FFMA 4x4 tiles
// (FFMA2 & mma.sync both measured slower; tcgen05 not compilable on sm_103),
// now with single-sync double-buffered k-panels to hide LDG latency.

#define NROWS 8192
#define DDIM  256
#define GCHUNKS 64          // gram K-chunks: 128 rows each
#define SCHUNKS 256         // norm/s blocks: 32 rows each
#define NTILES  10          // upper-triangle 64x64 tiles of the 4x4 tile grid

__device__ float  g_invn[NROWS];
__device__ float2 g_spart[SCHUNKS][DDIM];   // compensated fp32 pairs (hi, lo)
__device__ float2 g_s2[DDIM];
__device__ float  g_rinv[NROWS];
__device__ float  g_Mpart[GCHUNKS][NTILES][64 * 64];
__device__ float  g_M[DDIM * DDIM];

__device__ const int c_TI[NTILES] = {0,0,0,0,1,1,1,2,2,3};
__device__ const int c_TJ[NTILES] = {0,1,2,3,1,2,3,2,3,3};

// ---- error-free fp32 transforms ------------------------------------------
__device__ __forceinline__ void twoSum(float a, float b, float& s, float& e) {
    s = a + b;
    float bb = s - a;
    e = (a - (s - bb)) + (b - bb);
}
__device__ __forceinline__ void twoProd(float a, float b, float& p, float& e) {
    p = a * b;
    e = fmaf(a, b, -p);
}

// ---------------------------------------------------------------------------
// Kernel 1: per-row inverse norms + compensated fp32 partial column sums of
// X_hat. 256 blocks x 256 threads; block b handles rows [b*32, +32).
// ---------------------------------------------------------------------------
__global__ void __launch_bounds__(256) k_norm_s(const float* __restrict__ X) {
    __shared__ float invn_sh[32];
    const int row0 = blockIdx.x * 32;
    const int wid  = threadIdx.x >> 5;
    const int lane = threadIdx.x & 31;

    for (int r = wid; r < 32; r += 8) {
        const float4* p = reinterpret_cast<const float4*>(X + (size_t)(row0 + r) * DDIM);
        float ss = 0.f;
        #pragma unroll
        for (int q = 0; q < 2; q++) {
            float4 v = p[lane + q * 32];
            ss += v.x * v.x + v.y * v.y + v.z * v.z + v.w * v.w;
        }
        #pragma unroll
        for (int o = 16; o > 0; o >>= 1) ss += __shfl_xor_sync(0xffffffffu, ss, o);
        if (lane == 0) {
            float inv = 1.0f / fmaxf(sqrtf(ss), 1e-8f);
            invn_sh[r]       = inv;
            g_invn[row0 + r] = inv;
        }
    }
    __syncthreads();

    const int t = threadIdx.x;
    float s = 0.f, c = 0.f;
    #pragma unroll
    for (int r = 0; r < 32; r++) {
        float p, e, t1;
        twoProd(invn_sh[r], X[(size_t)(row0 + r) * DDIM + t], p, e);
        twoSum(s, p, s, t1);
        c += t1 + e;
    }
    g_spart[blockIdx.x][t] = make_float2(s, c);
}

// ---------------------------------------------------------------------------
// Kernel 2: partial Gram, upper-triangle tiles only (M is symmetric).
// grid = (64 k-chunks, 10 tiles), 256 threads, 4x4 register tile per thread.
// Double-buffered k-panels of 8, ONE sync per panel.
// ---------------------------------------------------------------------------
__global__ void __launch_bounds__(256) k_gram(const float* __restrict__ X) {
    __shared__ float SA[2][8][64];
    __shared__ float SB[2][8][64];

    const int c  = blockIdx.x;
    const int t  = blockIdx.y;
    const int ti = c_TI[t];
    const int tj = c_TJ[t];
    const int tx = threadIdx.x & 15;
    const int ty = (threadIdx.x >> 4) & 15;
    const int side = threadIdx.x >> 7;          // warps 0-3 load SA, 4-7 load SB
    const int li   = (threadIdx.x >> 4) & 7;    // stage row 0..7
    const int lf   = threadIdx.x & 15;          // float4 slot 0..15
    const int rowbase = c * 128;
    const int colbase = (side == 0 ? ti : tj) * 64;

    float T[4][4];
    #pragma unroll
    for (int i = 0; i < 4; i++)
        #pragma unroll
        for (int j = 0; j < 4; j++) T[i][j] = 0.f;

    // prologue: stage panel 0
    {
        const int gr = rowbase + li;
        float4 v = *reinterpret_cast<const float4*>(X + (size_t)gr * DDIM + colbase + lf * 4);
        if (side == 0) {
            const float sc = g_invn[gr];
            *reinterpret_cast<float4*>(&SA[0][li][lf * 4]) =
                make_float4(v.x * sc, v.y * sc, v.z * sc, v.w * sc);
        } else {
            *reinterpret_cast<float4*>(&SB[0][li][lf * 4]) = v;
        }
    }
    __syncthreads();

    for (int s = 0; s < 16; s++) {
        const int p = s & 1;
        float4 vn;
        float scn = 1.f;
        if (s < 15) {
            const int gr = rowbase + (s + 1) * 8 + li;
            vn = *reinterpret_cast<const float4*>(X + (size_t)gr * DDIM + colbase + lf * 4);
            if (side == 0) scn = g_invn[gr];
        }
        #pragma unroll
        for (int r = 0; r < 8; r++) {
            float4 a = *reinterpret_cast<const float4*>(&SA[p][r][ty * 4]);
            float4 b = *reinterpret_cast<const float4*>(&SB[p][r][tx * 4]);
            const float aa[4] = {a.x, a.y, a.z, a.w};
            const float bb[4] = {b.x, b.y, b.z, b.w};
            #pragma unroll
            for (int i = 0; i < 4; i++)
                #pragma unroll
                for (int j = 0; j < 4; j++) T[i][j] += aa[i] * bb[j];
        }
        if (s < 15) {
            if (side == 0)
                *reinterpret_cast<float4*>(&SA[p ^ 1][li][lf * 4]) =
                    make_float4(vn.x * scn, vn.y * scn, vn.z * scn, vn.w * scn);
            else
                *reinterpret_cast<float4*>(&SB[p ^ 1][li][lf * 4]) = vn;
        }
        __syncthreads();
    }

    float* out = &g_Mpart[c][t][0];
    #pragma unroll
    for (int i = 0; i < 4; i++)
        *reinterpret_cast<float4*>(&out[(ty * 4 + i) * 64 + tx * 4]) =
            make_float4(T[i][0], T[i][1], T[i][2], T[i][3]);
}

// ---------------------------------------------------------------------------
// Kernel 3: compensated fp32 reduce of Mpart (with symmetric mirror) and the
// s-partial pairs. 160 blocks x 256 threads cover 10*4096 upper-tile elems.
// ---------------------------------------------------------------------------
__global__ void __launch_bounds__(256) k_reduce() {
    const int idx = blockIdx.x * 256 + threadIdx.x;   // 0..40959
    const int t = idx >> 12;
    const int e = idx & 4095;
    float s = 0.f, comp = 0.f;
    #pragma unroll
    for (int c = 0; c < GCHUNKS; c++) {
        float t1;
        twoSum(s, g_Mpart[c][t][e], s, t1);
        comp += t1;
    }
    const float v = s + comp;
    const int k = c_TI[t] * 64 + (e >> 6);
    const int l = c_TJ[t] * 64 + (e & 63);
    if (k < l) {
        g_M[k * DDIM + l] = v;
        g_M[l * DDIM + k] = v;
    } else if (k == l) {
        g_M[k * DDIM + l] = v;
    } // k > l only inside diagonal tiles: mirror writes it

    if (blockIdx.x == 0) {
        float sa = 0.f, ca = 0.f;
        #pragma unroll 8
        for (int b = 0; b < SCHUNKS; b++) {
            float2 p = g_spart[b][threadIdx.x];
            float t1;
            twoSum(sa, p.x, sa, t1);
            ca += t1 + p.y;
        }
        g_s2[threadIdx.x] = make_float2(sa, ca);
    }
}

// ---------------------------------------------------------------------------
// Kernel 4: rinv[i] = 1 / (x_i . s) via fp32 Dot2, one row per warp.
// ---------------------------------------------------------------------------
__global__ void __launch_bounds__(256) k_rinv(const float* __restrict__ X) {
    __shared__ float2 s_sh[DDIM];
    s_sh[threadIdx.x] = g_s2[threadIdx.x];
    __syncthreads();
    const int wid  = threadIdx.x >> 5;
    const int lane = threadIdx.x & 31;
    const int row  = blockIdx.x * 8 + wid;

    const float4* xp4 = reinterpret_cast<const float4*>(X + (size_t)row * DDIM);
    float s = 0.f, c = 0.f;
    #pragma unroll
    for (int q = 0; q < 2; q++) {
        const int f = lane + q * 32;
        const float4 xv = xp4[f];
        const float xs[4] = {xv.x, xv.y, xv.z, xv.w};
        #pragma unroll
        for (int m = 0; m < 4; m++) {
            const float2 sv = s_sh[f * 4 + m];
            float p, e, t1;
            twoProd(xs[m], sv.x, p, e);
            e = fmaf(xs[m], sv.y, e);
            twoSum(s, p, s, t1);
            c += t1 + e;
        }
    }
    #pragma unroll
    for (int o = 16; o > 0; o >>= 1) {
        float s2 = __shfl_xor_sync(0xffffffffu, s, o);
        float c2 = __shfl_xor_sync(0xffffffffu, c, o);
        float t1;
        twoSum(s, s2, s, t1);
        c += c2 + t1;
    }
    if (lane == 0) {
        double den = (double)s + (double)c;
        g_rinv[row] = (float)(1.0 / den);
    }
}

// ---------------------------------------------------------------------------
// Kernel 5: OUT = (X @ M) * rinv rowwise.
// grid = (128 row tiles, 4 col tiles) = 512 blocks, 256 threads, 4x4/thread.
// Double-buffered k-panels of 8, ONE sync per panel.
// ---------------------------------------------------------------------------
__global__ void __launch_bounds__(256) k_out(const float* __restrict__ X,
                                             float* __restrict__ OUT) {
    __shared__ float SA[2][8][68];
    __shared__ float SB[2][8][64];

    const int row0 = blockIdx.x * 64;
    const int c0   = blockIdx.y * 64;
    const int tx   = threadIdx.x & 15;
    const int ty   = (threadIdx.x >> 4) & 15;

    const int ar = threadIdx.x >> 1;          // SA loader: row (tid<128)
    const int ah = threadIdx.x & 1;           // SA loader: k-half
    const int bi = (threadIdx.x >> 4) & 7;    // SB loader: stage row
    const int bf = threadIdx.x & 15;          // SB loader: float4 slot

    float T[4][4];
    #pragma unroll
    for (int i = 0; i < 4; i++)
        #pragma unroll
        for (int j = 0; j < 4; j++) T[i][j] = 0.f;

    // prologue: stage panel 0
    {
        float4 v;
        if (threadIdx.x < 128) {
            v = *reinterpret_cast<const float4*>(X + (size_t)(row0 + ar) * DDIM + ah * 4);
            SA[0][ah * 4 + 0][ar] = v.x;
            SA[0][ah * 4 + 1][ar] = v.y;
            SA[0][ah * 4 + 2][ar] = v.z;
            SA[0][ah * 4 + 3][ar] = v.w;
        } else {
            v = *reinterpret_cast<const float4*>(&g_M[bi * DDIM + c0 + bf * 4]);
            *reinterpret_cast<float4*>(&SB[0][bi][bf * 4]) = v;
        }
    }
    __syncthreads();

    for (int s = 0; s < 32; s++) {
        const int p = s & 1;
        float4 vn;
        if (s < 31) {
            const int k1 = (s + 1) * 8;
            if (threadIdx.x < 128)
                vn = *reinterpret_cast<const float4*>(X + (size_t)(row0 + ar) * DDIM + k1 + ah * 4);
            else
                vn = *reinterpret_cast<const float4*>(&g_M[(k1 + bi) * DDIM + c0 + bf * 4]);
        }
        #pragma unroll
        for (int r = 0; r < 8; r++) {
            float4 a = *reinterpret_cast<const float4*>(&SA[p][r][ty * 4]);
            float4 b = *reinterpret_cast<const float4*>(&SB[p][r][tx * 4]);
            const float aa[4] = {a.x, a.y, a.z, a.w};
            const float bb[4] = {b.x, b.y, b.z, b.w};
            #pragma unroll
            for (int i = 0; i < 4; i++)
                #pragma unroll
                for (int j = 0; j < 4; j++) T[i][j] += aa[i] * bb[j];
        }
        if (s < 31) {
            if (threadIdx.x < 128) {
                SA[p ^ 1][ah * 4 + 0][ar] = vn.x;
                SA[p ^ 1][ah * 4 + 1][ar] = vn.y;
                SA[p ^ 1][ah * 4 + 2][ar] = vn.z;
                SA[p ^ 1][ah * 4 + 3][ar] = vn.w;
            } else {
                *reinterpret_cast<float4*>(&SB[p ^ 1][bi][bf * 4]) = vn;
            }
        }
        __syncthreads();
    }

    #pragma unroll
    for (int i = 0; i < 4; i++) {
        const int m = row0 + ty * 4 + i;
        const float rv = g_rinv[m];
        *reinterpret_cast<float4*>(&OUT[(size_t)m * DDIM + c0 + tx * 4]) =
            make_float4(T[i][0] * rv, T[i][1] * rv, T[i][2] * rv, T[i][3] * rv);
    }
}

extern "C" void kernel_launch(void* const* d_in, const int* in_sizes, int n_in,
                              void* d_out, int out_size) {
    (void)in_sizes; (void)n_in; (void)out_size;
    const float* X = (const float*)d_in[0];
    float* OUT     = (float*)d_out;

    k_norm_s<<<SCHUNKS, 256>>>(X);
    k_gram<<<dim3(GCHUNKS, NTILES), 256>>>(X);
    k_reduce<<<160, 256>>>();
    k_rinv<<<1024, 256>>>(X);
    k_out<<<dim3(128, 4), 256>>>(X, OUT);
}

// round 13
// speedup vs baseline: 1.3840x; 1.0276x over previous
#include <cuda_runtime.h>
#include <math.h>

// Problem: tensor [8192, 256] fp32.
// out = (adj @ X) where adj = rownorm(cosine_sim(X)).
// Factored: M = X_hat^T X (256x256, SYMMETRIC), s = sum_j x_hat_j (256),
//           out[i] = (x_i @ M) / (x_i . s)   (inv-norm cancels).
// Denominator via compensated fp32 Dot2. GEMMs: scalar FFMA 4x4 tiles,
// double-buffered panels. rinv computation is folded into k_out's grid as
// its first 128 blocks (overlaps the GEMM mainloop); GEMM epilogues spin on
// a release counter (threadFenceReduction pattern).

#define NROWS 8192
#define DDIM  256
#define GCHUNKS 64          // gram K-chunks: 128 rows each
#define SCHUNKS 256         // norm/s blocks: 32 rows each
#define NTILES  10          // upper-triangle 64x64 tiles of the 4x4 tile grid
#define RINV_BLOCKS 128

__device__ float  g_invn[NROWS];
__device__ float2 g_spart[SCHUNKS][DDIM];   // compensated fp32 pairs (hi, lo)
__device__ float2 g_s2[DDIM];
__device__ float  g_rinv[NROWS];
__device__ float  g_Mpart[GCHUNKS][NTILES][64 * 64];
__device__ float  g_M[DDIM * DDIM];
__device__ int    g_done;                   // zeroed per launch via memsetAsync

__device__ const int c_TI[NTILES] = {0,0,0,0,1,1,1,2,2,3};
__device__ const int c_TJ[NTILES] = {0,1,2,3,1,2,3,2,3,3};

// ---- error-free fp32 transforms ------------------------------------------
__device__ __forceinline__ void twoSum(float a, float b, float& s, float& e) {
    s = a + b;
    float bb = s - a;
    e = (a - (s - bb)) + (b - bb);
}
__device__ __forceinline__ void twoProd(float a, float b, float& p, float& e) {
    p = a * b;
    e = fmaf(a, b, -p);
}

// ---------------------------------------------------------------------------
// Kernel 1: per-row inverse norms + compensated fp32 partial column sums of
// X_hat. 256 blocks x 256 threads; block b handles rows [b*32, +32).
// ---------------------------------------------------------------------------
__global__ void __launch_bounds__(256) k_norm_s(const float* __restrict__ X) {
    __shared__ float invn_sh[32];
    const int row0 = blockIdx.x * 32;
    const int wid  = threadIdx.x >> 5;
    const int lane = threadIdx.x & 31;

    for (int r = wid; r < 32; r += 8) {
        const float4* p = reinterpret_cast<const float4*>(X + (size_t)(row0 + r) * DDIM);
        float ss = 0.f;
        #pragma unroll
        for (int q = 0; q < 2; q++) {
            float4 v = p[lane + q * 32];
            ss += v.x * v.x + v.y * v.y + v.z * v.z + v.w * v.w;
        }
        #pragma unroll
        for (int o = 16; o > 0; o >>= 1) ss += __shfl_xor_sync(0xffffffffu, ss, o);
        if (lane == 0) {
            float inv = 1.0f / fmaxf(sqrtf(ss), 1e-8f);
            invn_sh[r]       = inv;
            g_invn[row0 + r] = inv;
        }
    }
    __syncthreads();

    const int t = threadIdx.x;
    float s = 0.f, c = 0.f;
    #pragma unroll
    for (int r = 0; r < 32; r++) {
        float p, e, t1;
        twoProd(invn_sh[r], X[(size_t)(row0 + r) * DDIM + t], p, e);
        twoSum(s, p, s, t1);
        c += t1 + e;
    }
    g_spart[blockIdx.x][t] = make_float2(s, c);
}

// ---------------------------------------------------------------------------
// Kernel 2: partial Gram, upper-triangle tiles only (M is symmetric).
// grid = (64 k-chunks, 10 tiles), 256 threads, 4x4 register tile per thread.
// Double-buffered k-panels of 8, ONE sync per panel.
// ---------------------------------------------------------------------------
__global__ void __launch_bounds__(256) k_gram(const float* __restrict__ X) {
    __shared__ float SA[2][8][64];
    __shared__ float SB[2][8][64];

    const int c  = blockIdx.x;
    const int t  = blockIdx.y;
    const int ti = c_TI[t];
    const int tj = c_TJ[t];
    const int tx = threadIdx.x & 15;
    const int ty = (threadIdx.x >> 4) & 15;
    const int side = threadIdx.x >> 7;          // warps 0-3 load SA, 4-7 load SB
    const int li   = (threadIdx.x >> 4) & 7;    // stage row 0..7
    const int lf   = threadIdx.x & 15;          // float4 slot 0..15
    const int rowbase = c * 128;
    const int colbase = (side == 0 ? ti : tj) * 64;

    float T[4][4];
    #pragma unroll
    for (int i = 0; i < 4; i++)
        #pragma unroll
        for (int j = 0; j < 4; j++) T[i][j] = 0.f;

    // prologue: stage panel 0
    {
        const int gr = rowbase + li;
        float4 v = *reinterpret_cast<const float4*>(X + (size_t)gr * DDIM + colbase + lf * 4);
        if (side == 0) {
            const float sc = g_invn[gr];
            *reinterpret_cast<float4*>(&SA[0][li][lf * 4]) =
                make_float4(v.x * sc, v.y * sc, v.z * sc, v.w * sc);
        } else {
            *reinterpret_cast<float4*>(&SB[0][li][lf * 4]) = v;
        }
    }
    __syncthreads();

    for (int s = 0; s < 16; s++) {
        const int p = s & 1;
        float4 vn;
        float scn = 1.f;
        if (s < 15) {
            const int gr = rowbase + (s + 1) * 8 + li;
            vn = *reinterpret_cast<const float4*>(X + (size_t)gr * DDIM + colbase + lf * 4);
            if (side == 0) scn = g_invn[gr];
        }
        #pragma unroll
        for (int r = 0; r < 8; r++) {
            float4 a = *reinterpret_cast<const float4*>(&SA[p][r][ty * 4]);
            float4 b = *reinterpret_cast<const float4*>(&SB[p][r][tx * 4]);
            const float aa[4] = {a.x, a.y, a.z, a.w};
            const float bb[4] = {b.x, b.y, b.z, b.w};
            #pragma unroll
            for (int i = 0; i < 4; i++)
                #pragma unroll
                for (int j = 0; j < 4; j++) T[i][j] += aa[i] * bb[j];
        }
        if (s < 15) {
            if (side == 0)
                *reinterpret_cast<float4*>(&SA[p ^ 1][li][lf * 4]) =
                    make_float4(vn.x * scn, vn.y * scn, vn.z * scn, vn.w * scn);
            else
                *reinterpret_cast<float4*>(&SB[p ^ 1][li][lf * 4]) = vn;
        }
        __syncthreads();
    }

    float* out = &g_Mpart[c][t][0];
    #pragma unroll
    for (int i = 0; i < 4; i++)
        *reinterpret_cast<float4*>(&out[(ty * 4 + i) * 64 + tx * 4]) =
            make_float4(T[i][0], T[i][1], T[i][2], T[i][3]);
}

// ---------------------------------------------------------------------------
// Kernel 3: compensated fp32 reduce of Mpart (with symmetric mirror) and the
// s-partial pairs. 160 blocks x 256 threads cover 10*4096 upper-tile elems.
// ---------------------------------------------------------------------------
__global__ void __launch_bounds__(256) k_reduce() {
    const int idx = blockIdx.x * 256 + threadIdx.x;   // 0..40959
    const int t = idx >> 12;
    const int e = idx & 4095;
    float s = 0.f, comp = 0.f;
    #pragma unroll
    for (int c = 0; c < GCHUNKS; c++) {
        float t1;
        twoSum(s, g_Mpart[c][t][e], s, t1);
        comp += t1;
    }
    const float v = s + comp;
    const int k = c_TI[t] * 64 + (e >> 6);
    const int l = c_TJ[t] * 64 + (e & 63);
    if (k < l) {
        g_M[k * DDIM + l] = v;
        g_M[l * DDIM + k] = v;
    } else if (k == l) {
        g_M[k * DDIM + l] = v;
    } // k > l only inside diagonal tiles: mirror writes it

    if (blockIdx.x == 0) {
        float sa = 0.f, ca = 0.f;
        #pragma unroll 8
        for (int b = 0; b < SCHUNKS; b++) {
            float2 p = g_spart[b][threadIdx.x];
            float t1;
            twoSum(sa, p.x, sa, t1);
            ca += t1 + p.y;
        }
        g_s2[threadIdx.x] = make_float2(sa, ca);
    }
}

// ---------------------------------------------------------------------------
// Kernel 4: fused rinv + GEMM. 1-D grid of 640 blocks:
//   blocks [0, 128):  rinv for rows [bid*64, +64)  (8 warps x 8 rows, Dot2 —
//                     identical arithmetic to the former k_rinv), then
//                     threadfence + counter release.
//   blocks [128,640): OUT = (X @ M) * rinv for tile (rb = id>>2, cb = id&3);
//                     epilogue spins on the counter (always satisfied long
//                     before the ~25us numerator completes).
// ---------------------------------------------------------------------------
__global__ void __launch_bounds__(256) k_out(const float* __restrict__ X,
                                             float* __restrict__ OUT) {
    const int bid = blockIdx.x;
    const int wid  = threadIdx.x >> 5;
    const int lane = threadIdx.x & 31;

    if (bid < RINV_BLOCKS) {
        __shared__ float2 s_sh[DDIM];
        s_sh[threadIdx.x] = g_s2[threadIdx.x];
        __syncthreads();
        #pragma unroll
        for (int rr = 0; rr < 8; rr++) {
            const int row = bid * 64 + wid * 8 + rr;
            const float4* xp4 = reinterpret_cast<const float4*>(X + (size_t)row * DDIM);
            float s = 0.f, c = 0.f;
            #pragma unroll
            for (int q = 0; q < 2; q++) {
                const int f = lane + q * 32;
                const float4 xv = xp4[f];
                const float xs[4] = {xv.x, xv.y, xv.z, xv.w};
                #pragma unroll
                for (int m = 0; m < 4; m++) {
                    const float2 sv = s_sh[f * 4 + m];
                    float p, e, t1;
                    twoProd(xs[m], sv.x, p, e);
                    e = fmaf(xs[m], sv.y, e);
                    twoSum(s, p, s, t1);
                    c += t1 + e;
                }
            }
            #pragma unroll
            for (int o = 16; o > 0; o >>= 1) {
                float s2 = __shfl_xor_sync(0xffffffffu, s, o);
                float c2 = __shfl_xor_sync(0xffffffffu, c, o);
                float t1;
                twoSum(s, s2, s, t1);
                c += c2 + t1;
            }
            if (lane == 0) {
                double den = (double)s + (double)c;
                g_rinv[row] = (float)(1.0 / den);
            }
        }
        __threadfence();
        __syncthreads();
        if (threadIdx.x == 0) atomicAdd(&g_done, 1);
        return;
    }

    // ---- GEMM part ----
    __shared__ float SA[2][8][68];
    __shared__ float SB[2][8][64];

    const int id2  = bid - RINV_BLOCKS;
    const int row0 = (id2 >> 2) * 64;
    const int c0   = (id2 & 3) * 64;
    const int tx   = threadIdx.x & 15;
    const int ty   = (threadIdx.x >> 4) & 15;

    const int ar = threadIdx.x >> 1;          // SA loader: row (tid<128)
    const int ah = threadIdx.x & 1;           // SA loader: k-half
    const int bi = (threadIdx.x >> 4) & 7;    // SB loader: stage row
    const int bf = threadIdx.x & 15;          // SB loader: float4 slot

    float T[4][4];
    #pragma unroll
    for (int i = 0; i < 4; i++)
        #pragma unroll
        for (int j = 0; j < 4; j++) T[i][j] = 0.f;

    // prologue: stage panel 0
    {
        float4 v;
        if (threadIdx.x < 128) {
            v = *reinterpret_cast<const float4*>(X + (size_t)(row0 + ar) * DDIM + ah * 4);
            SA[0][ah * 4 + 0][ar] = v.x;
            SA[0][ah * 4 + 1][ar] = v.y;
            SA[0][ah * 4 + 2][ar] = v.z;
            SA[0][ah * 4 + 3][ar] = v.w;
        } else {
            v = *reinterpret_cast<const float4*>(&g_M[bi * DDIM + c0 + bf * 4]);
            *reinterpret_cast<float4*>(&SB[0][bi][bf * 4]) = v;
        }
    }
    __syncthreads();

    for (int s = 0; s < 32; s++) {
        const int p = s & 1;
        float4 vn;
        if (s < 31) {
            const int k1 = (s + 1) * 8;
            if (threadIdx.x < 128)
                vn = *reinterpret_cast<const float4*>(X + (size_t)(row0 + ar) * DDIM + k1 + ah * 4);
            else
                vn = *reinterpret_cast<const float4*>(&g_M[(k1 + bi) * DDIM + c0 + bf * 4]);
        }
        #pragma unroll
        for (int r = 0; r < 8; r++) {
            float4 a = *reinterpret_cast<const float4*>(&SA[p][r][ty * 4]);
            float4 b = *reinterpret_cast<const float4*>(&SB[p][r][tx * 4]);
            const float aa[4] = {a.x, a.y, a.z, a.w};
            const float bb[4] = {b.x, b.y, b.z, b.w};
            #pragma unroll
            for (int i = 0; i < 4; i++)
                #pragma unroll
                for (int j = 0; j < 4; j++) T[i][j] += aa[i] * bb[j];
        }
        if (s < 31) {
            if (threadIdx.x < 128) {
                SA[p ^ 1][ah * 4 + 0][ar] = vn.x;
                SA[p ^ 1][ah * 4 + 1][ar] = vn.y;
                SA[p ^ 1][ah * 4 + 2][ar] = vn.z;
                SA[p ^ 1][ah * 4 + 3][ar] = vn.w;
            } else {
                *reinterpret_cast<float4*>(&SB[p ^ 1][bi][bf * 4]) = vn;
            }
        }
        __syncthreads();
    }

    // wait for rinv release (in practice already satisfied)
    if (threadIdx.x == 0) {
        while (*(volatile int*)&g_done < RINV_BLOCKS) { }
    }
    __syncthreads();

    #pragma unroll
    for (int i = 0; i < 4; i++) {
        const int m = row0 + ty * 4 + i;
        const float rv = __ldcg(&g_rinv[m]);
        *reinterpret_cast<float4*>(&OUT[(size_t)m * DDIM + c0 + tx * 4]) =
            make_float4(T[i][0] * rv, T[i][1] * rv, T[i][2] * rv, T[i][3] * rv);
    }
}

extern "C" void kernel_launch(void* const* d_in, const int* in_sizes, int n_in,
                              void* d_out, int out_size) {
    (void)in_sizes; (void)n_in; (void)out_size;
    const float* X = (const float*)d_in[0];
    float* OUT     = (float*)d_out;

    void* donep = 0;
    cudaGetSymbolAddress(&donep, g_done);
    cudaMemsetAsync(donep, 0, sizeof(int));

    k_norm_s<<<SCHUNKS, 256>>>(X);
    k_gram<<<dim3(GCHUNKS, NTILES), 256>>>(X);
    k_reduce<<<160, 256>>>();
    k_out<<<RINV_BLOCKS + 512, 256>>>(X, OUT);
}